// round 14
// baseline (speedup 1.0000x reference)
#include <cuda_runtime.h>
#include <cstdint>

#define NFRAMES 8
#define SEQLEN  25
#define BSZ     256
#define DF      16384
#define LAMF    0.1f
#define INVLAM  10.0f
#define SCHUNK  5
#define NCHUNK  5
#define THREADS 512
#define RING    10
#define PF      8
#define NFR_TOT (SCHUNK * NFRAMES)
#define PSTRIDE 68          // 64 partial cols + 4 pad (bank-free stores)

// ---------- sm_103a packed fp32 FMA ----------
__device__ __forceinline__ unsigned long long ffma2(unsigned long long a,
                                                    unsigned long long b,
                                                    unsigned long long c) {
    unsigned long long d;
    asm("fma.rn.f32x2 %0, %1, %2, %3;" : "=l"(d) : "l"(a), "l"(b), "l"(c));
    return d;
}
__device__ __forceinline__ float pairsum(unsigned long long v) {
    float lo, hi;
    asm("mov.b64 {%0,%1}, %2;" : "=f"(lo), "=f"(hi) : "l"(v));
    return lo + hi;
}
__device__ __forceinline__ float warp_sum(float v) {
    v += __shfl_xor_sync(0xffffffffu, v, 16);
    v += __shfl_xor_sync(0xffffffffu, v, 8);
    v += __shfl_xor_sync(0xffffffffu, v, 4);
    v += __shfl_xor_sync(0xffffffffu, v, 2);
    v += __shfl_xor_sync(0xffffffffu, v, 1);
    return v;
}

// Truncated multi-value reduction: 8 values, 3 SHFL stages (7 SHFLs).
// v[0] at lane l = sum of value bitrev3(l&7) over l's aligned 8-lane group.
__device__ __forceinline__ void reduce8_3(float v[8], unsigned lane) {
#pragma unroll
    for (int k = 0; k < 4; k++) {
        float send = (lane & 1) ? v[k] : v[k + 4];
        float keep = (lane & 1) ? v[k + 4] : v[k];
        v[k] = keep + __shfl_xor_sync(0xffffffffu, send, 1);
    }
#pragma unroll
    for (int k = 0; k < 2; k++) {
        float send = (lane & 2) ? v[k] : v[k + 2];
        float keep = (lane & 2) ? v[k + 2] : v[k];
        v[k] = keep + __shfl_xor_sync(0xffffffffu, send, 2);
    }
    {
        float send = (lane & 4) ? v[0] : v[1];
        float keep = (lane & 4) ? v[1] : v[0];
        v[0] = keep + __shfl_xor_sync(0xffffffffu, send, 4);
    }
}
__device__ __forceinline__ int bitrev3(int l) {
    return ((l & 1) << 2) | (l & 2) | ((l & 4) >> 2);
}

// ---------- cp.async helpers ----------
__device__ __forceinline__ void cp16(unsigned smem_addr, const void* gptr) {
    asm volatile("cp.async.cg.shared.global [%0], [%1], 16;\n"
                 :: "r"(smem_addr), "l"(gptr));
}
__device__ __forceinline__ void cp_commit() {
    asm volatile("cp.async.commit_group;\n");
}
template <int N>
__device__ __forceinline__ void cp_wait() {
    asm volatile("cp.async.wait_group %0;\n" :: "n"(N));
}

// fast stable pairwise lam*logsumexp (MUFU ex2/lg2)
__device__ __forceinline__ float lsep(float a, float b) {
    float m = fmaxf(a, b);
    float d = fabsf(a - b);
    return fmaf(LAMF, __logf(1.0f + __expf(-d * INVLAM)), m);
}

// runtime-transposed OTAM soft-DP on the 8x8 matrix
__device__ float dp8r(const float* __restrict__ d,
                      const float* __restrict__ sn,
                      const float* __restrict__ tn, bool tr) {
    float prev[8];
#pragma unroll
    for (int r = 0; r < 8; r++) {
        int rr = tr ? 0 : r, cc = tr ? r : 0;
        prev[r] = d[rr * 8 + cc] * sn[rr] * tn[cc];
    }
#pragma unroll
    for (int c = 1; c < 8; c++) {
        float nw[8];
        {
            int rr = tr ? c : 0, cc = tr ? 0 : c;
            nw[0] = prev[0] + d[rr * 8 + cc] * sn[rr] * tn[cc];
        }
#pragma unroll
        for (int r = 1; r < 8; r++) {
            int rr = tr ? c : r, cc = tr ? r : c;
            nw[r] = lsep(prev[r - 1], prev[r]) + d[rr * 8 + cc] * sn[rr] * tn[cc];
        }
#pragma unroll
        for (int r = 0; r < 8; r++) prev[r] = nw[r];
    }
    float m = prev[0];
#pragma unroll
    for (int r = 1; r < 8; r++) m = fmaxf(m, prev[r]);
    float s = 0.0f;
#pragma unroll
    for (int r = 0; r < 8; r++) s += __expf((prev[r] - m) * INVLAM);
    return fmaf(LAMF, __logf(s), m);
}

__global__ void __launch_bounds__(THREADS, 2)
otam_kernel(const ulonglong2* __restrict__ sup,   // [25,256,16384] f32 as ull2
            const ulonglong2* __restrict__ tgt,   // [256,16384]    f32 as ull2
            float* __restrict__ out)              // [25,256]
{
    extern __shared__ ulonglong2 ring[];          // [RING][512] x 16B = 80KB

    // 72 rows (64 dots + 8 norms) x 64 partials, stride 68
    __shared__ __align__(16) float bufAll[72 * PSTRIDE];
    __shared__ float dot_sh[64];
    __shared__ float sninv_sh[8];
    __shared__ float tninv_sh[8];

    const int t     = threadIdx.x;
    const int w     = t >> 5;                     // 0..15
    const unsigned lane = t & 31;
    const int g     = (int)(lane >> 3);           // 8-lane group 0..3
    const int col64 = w * 4 + g;                  // partial slot 0..63
    const int b     = blockIdx.x;
    const int chunk = blockIdx.y;

    unsigned ring_base = (unsigned)__cvta_generic_to_shared(ring);
    const ulonglong2* gbase = sup + ((size_t)(chunk * SCHUNK) * BSZ + b) * (DF / 4);
    const size_t sstride = (size_t)BSZ * (DF / 4);

    auto issue = [&](int f) {   // always commits: wait_group math stays exact
        if (f < NFR_TOT) {
            const int sl = f >> 3, i = f & 7;
            const ulonglong2* src = gbase + (size_t)sl * sstride + (size_t)i * 512;
            const int slot = f % RING;
            cp16(ring_base + (unsigned)(slot * 512 + t) * 16, src + t);
        }
        cp_commit();
    };

#pragma unroll
    for (int f = 0; f < PF; f++) issue(f);

    // ---- target frames in registers: 8 frames x 4 floats/thread ----
    const ulonglong2* tb = tgt + (size_t)b * (DF / 4);
    ulonglong2 tva[8];
#pragma unroll
    for (int j = 0; j < 8; j++) tva[j] = tb[j * 512 + t];

    // ---- target norms (once per block; bufAll as scratch) ----
#pragma unroll
    for (int j = 0; j < 8; j++) {
        unsigned long long n2 = 0ull;
        n2 = ffma2(tva[j].x, tva[j].x, n2);
        n2 = ffma2(tva[j].y, tva[j].y, n2);
        float v = warp_sum(pairsum(n2));
        if (lane == 0) bufAll[j * PSTRIDE + w] = v;
    }
    __syncthreads();
    if (t < 8) {
        float s = 0.0f;
#pragma unroll
        for (int ww = 0; ww < 16; ww++) s += bufAll[t * PSTRIDE + ww];
        tninv_sh[t] = 1.0f / fmaxf(sqrtf(s), 1e-12f);
    }
    __syncthreads();

    // ---- main streaming loop: 5 s-values x 8 frames ----
    for (int ss = 0; ss < SCHUNK; ss++) {
        const int s = chunk * SCHUNK + ss;
        float nrm[8];
#pragma unroll
        for (int i = 0; i < 8; i++) {
            const int f = ss * 8 + i;
            cp_wait<PF - 1>();                       // group f complete (exact)
            const int slot = f % RING;
            ulonglong2 A = ring[slot * 512 + t];
            issue(f + PF);

            unsigned long long acc[8];
#pragma unroll
            for (int j = 0; j < 8; j++) acc[j] = 0ull;
            unsigned long long n2 = 0ull;
            n2 = ffma2(A.x, A.x, n2);
            n2 = ffma2(A.y, A.y, n2);
#pragma unroll
            for (int j = 0; j < 8; j++) {
                acc[j] = ffma2(A.x, tva[j].x, acc[j]);
                acc[j] = ffma2(A.y, tva[j].y, acc[j]);
            }
            nrm[i] = pairsum(n2);
            float d[8];
#pragma unroll
            for (int j = 0; j < 8; j++) d[j] = pairsum(acc[j]);
            reduce8_3(d, lane);
            bufAll[(i * 8 + bitrev3((int)(lane & 7))) * PSTRIDE + col64] = d[0];
        }
        reduce8_3(nrm, lane);
        bufAll[(64 + bitrev3((int)(lane & 7))) * PSTRIDE + col64] = nrm[0];

        __syncthreads();
        if (t < 72) {                                // sum 64 partials per row
            const float4* p = (const float4*)(bufAll + t * PSTRIDE);
            float ssum = 0.0f;
#pragma unroll
            for (int k = 0; k < 16; k++) {
                float4 v4 = p[k];
                ssum += (v4.x + v4.y) + (v4.z + v4.w);
            }
            if (t < 64) dot_sh[t] = ssum;
            else        sninv_sh[t - 64] = 1.0f / fmaxf(sqrtf(ssum), 1e-12f);
        }
        __syncthreads();
        if (w == 0) {                                // DP: warp-parallel, both views
            float r = dp8r(dot_sh, sninv_sh, tninv_sh, (lane & 1) != 0);
            float o = __shfl_xor_sync(0xffffffffu, r, 1);
            if (lane == 0) out[s * BSZ + b] = 0.5f * (r + o);
        }
    }
}

extern "C" void kernel_launch(void* const* d_in, const int* in_sizes, int n_in,
                              void* d_out, int out_size) {
    const ulonglong2* sup = (const ulonglong2*)d_in[0];
    const ulonglong2* tgt = (const ulonglong2*)d_in[1];
    float* out = (float*)d_out;
    (void)in_sizes; (void)n_in; (void)out_size;

    const int smem_bytes = RING * 512 * 16;        // 80KB dynamic ring
    static bool attr_done = false;                  // idempotent; host-side only
    if (!attr_done) {
        cudaFuncSetAttribute(otam_kernel,
                             cudaFuncAttributeMaxDynamicSharedMemorySize,
                             smem_bytes);
        attr_done = true;
    }

    dim3 grid(BSZ, NCHUNK);
    otam_kernel<<<grid, THREADS, smem_bytes>>>(sup, tgt, out);
}

// round 15
// speedup vs baseline: 2.3369x; 2.3369x over previous
#include <cuda_runtime.h>
#include <cstdint>

#define NFRAMES 8
#define SEQLEN  25
#define BSZ     256
#define DF      16384
#define LAMF    0.1f
#define INVLAM  10.0f
#define SCHUNK  5
#define NCHUNK  5
#define THREADS 256
#define RING    10
#define PF      8
#define NFR_TOT (SCHUNK * NFRAMES)
#define PSTRIDE 36          // 32 partial cols + 4 pad

// ---------- sm_103a packed fp32 FMA ----------
__device__ __forceinline__ unsigned long long ffma2(unsigned long long a,
                                                    unsigned long long b,
                                                    unsigned long long c) {
    unsigned long long d;
    asm("fma.rn.f32x2 %0, %1, %2, %3;" : "=l"(d) : "l"(a), "l"(b), "l"(c));
    return d;
}
__device__ __forceinline__ float pairsum(unsigned long long v) {
    float lo, hi;
    asm("mov.b64 {%0,%1}, %2;" : "=f"(lo), "=f"(hi) : "l"(v));
    return lo + hi;
}

__device__ __forceinline__ int bitrev3(int l) {
    return ((l & 1) << 2) | (l & 2) | ((l & 4) >> 2);
}

// SELECT-FREE multi-value reduction. Requires value slot k at lane l to hold
// quantity index (k ^ bitrev3(l&7)). Then v[0] at lane l = full 8-lane-group
// sum of quantity bitrev3(l&7). 7 SHFL + 7 FADD, zero selects.
__device__ __forceinline__ void reduce8_free(float v[8]) {
#pragma unroll
    for (int k = 0; k < 4; k++) v[k] += __shfl_xor_sync(0xffffffffu, v[k + 4], 1);
#pragma unroll
    for (int k = 0; k < 2; k++) v[k] += __shfl_xor_sync(0xffffffffu, v[k + 2], 2);
    v[0] += __shfl_xor_sync(0xffffffffu, v[1], 4);
}

// selecty variant for values indexed identically on all lanes (support norms;
// once per s-iter, amortized). v[0] at lane l = sum of value bitrev3(l&7).
__device__ __forceinline__ void reduce8_3(float v[8], unsigned lane) {
#pragma unroll
    for (int k = 0; k < 4; k++) {
        float send = (lane & 1) ? v[k] : v[k + 4];
        float keep = (lane & 1) ? v[k + 4] : v[k];
        v[k] = keep + __shfl_xor_sync(0xffffffffu, send, 1);
    }
#pragma unroll
    for (int k = 0; k < 2; k++) {
        float send = (lane & 2) ? v[k] : v[k + 2];
        float keep = (lane & 2) ? v[k + 2] : v[k];
        v[k] = keep + __shfl_xor_sync(0xffffffffu, send, 2);
    }
    {
        float send = (lane & 4) ? v[0] : v[1];
        float keep = (lane & 4) ? v[1] : v[0];
        v[0] = keep + __shfl_xor_sync(0xffffffffu, send, 4);
    }
}

// ---------- cp.async helpers ----------
__device__ __forceinline__ void cp16(unsigned smem_addr, const void* gptr) {
    asm volatile("cp.async.cg.shared.global [%0], [%1], 16;\n"
                 :: "r"(smem_addr), "l"(gptr));
}
__device__ __forceinline__ void cp_commit() {
    asm volatile("cp.async.commit_group;\n");
}
template <int N>
__device__ __forceinline__ void cp_wait() {
    asm volatile("cp.async.wait_group %0;\n" :: "n"(N));
}

// fast stable pairwise lam*logsumexp (MUFU ex2/lg2)
__device__ __forceinline__ float lsep(float a, float b) {
    float m = fmaxf(a, b);
    float d = fabsf(a - b);
    return fmaf(LAMF, __logf(1.0f + __expf(-d * INVLAM)), m);
}

// runtime-transposed OTAM soft-DP on the 8x8 matrix
__device__ float dp8r(const float* __restrict__ d,
                      const float* __restrict__ sn,
                      const float* __restrict__ tn, bool tr) {
    float prev[8];
#pragma unroll
    for (int r = 0; r < 8; r++) {
        int rr = tr ? 0 : r, cc = tr ? r : 0;
        prev[r] = d[rr * 8 + cc] * sn[rr] * tn[cc];
    }
#pragma unroll
    for (int c = 1; c < 8; c++) {
        float nw[8];
        {
            int rr = tr ? c : 0, cc = tr ? 0 : c;
            nw[0] = prev[0] + d[rr * 8 + cc] * sn[rr] * tn[cc];
        }
#pragma unroll
        for (int r = 1; r < 8; r++) {
            int rr = tr ? c : r, cc = tr ? r : c;
            nw[r] = lsep(prev[r - 1], prev[r]) + d[rr * 8 + cc] * sn[rr] * tn[cc];
        }
#pragma unroll
        for (int r = 0; r < 8; r++) prev[r] = nw[r];
    }
    float m = prev[0];
#pragma unroll
    for (int r = 1; r < 8; r++) m = fmaxf(m, prev[r]);
    float s = 0.0f;
#pragma unroll
    for (int r = 0; r < 8; r++) s += __expf((prev[r] - m) * INVLAM);
    return fmaf(LAMF, __logf(s), m);
}

__global__ void __launch_bounds__(THREADS, 2)
otam_kernel(const ulonglong2* __restrict__ sup,   // [25,256,16384] f32 as ull2
            const ulonglong2* __restrict__ tgt,   // [256,16384]    f32 as ull2
            float* __restrict__ out)              // [25,256]
{
    extern __shared__ ulonglong2 ring[];          // [RING][512] x 16B = 80KB

    __shared__ __align__(16) float bufAll[2][72 * PSTRIDE];  // double-buffered partials
    __shared__ float dotsum[SCHUNK][72];          // [s][0..63 dots | 64..71 sninv]
    __shared__ float tninv_sh[8];

    const int t     = threadIdx.x;
    const int w     = t >> 5;
    const unsigned lane = t & 31;
    const int g     = (int)(lane >> 3);           // 8-lane group 0..3
    const int col32 = w * 4 + g;                  // partial slot 0..31
    const int perm  = bitrev3((int)(lane & 7));   // data-placement permutation
    const int b     = blockIdx.x;
    const int chunk = blockIdx.y;

    unsigned ring_base = (unsigned)__cvta_generic_to_shared(ring);
    const ulonglong2* gbase = sup + ((size_t)(chunk * SCHUNK) * BSZ + b) * (DF / 4);
    const size_t sstride = (size_t)BSZ * (DF / 4);

    auto issue = [&](int f) {   // always commits: wait_group math stays exact
        if (f < NFR_TOT) {
            const int sl = f >> 3, i = f & 7;
            const ulonglong2* src = gbase + (size_t)sl * sstride + (size_t)i * 512;
            const int slot = f % RING;
            cp16(ring_base + (unsigned)((slot * 2 + 0) * 256 + t) * 16, src + t);
            cp16(ring_base + (unsigned)((slot * 2 + 1) * 256 + t) * 16, src + 256 + t);
        }
        cp_commit();
    };

#pragma unroll
    for (int f = 0; f < PF; f++) issue(f);

    // ---- target frames, slot-PERMUTED: tva[k] holds frame (k ^ perm) ----
    const ulonglong2* tb = tgt + (size_t)b * (DF / 4);
    unsigned long long tva[8][4];
#pragma unroll
    for (int k = 0; k < 8; k++) {
        const int j = k ^ perm;
        ulonglong2 a = tb[j * 512 + t];
        ulonglong2 c = tb[j * 512 + 256 + t];
        tva[k][0] = a.x; tva[k][1] = a.y; tva[k][2] = c.x; tva[k][3] = c.y;
    }
    // ---- target norms: select-free reduce; lands at logical frame perm ----
    {
        float tn[8];
#pragma unroll
        for (int k = 0; k < 8; k++) {
            unsigned long long n2 = 0ull;
#pragma unroll
            for (int c = 0; c < 4; c++) n2 = ffma2(tva[k][c], tva[k][c], n2);
            tn[k] = pairsum(n2);
        }
        reduce8_free(tn);
        bufAll[0][perm * PSTRIDE + col32] = tn[0];
    }
    __syncthreads();
    if (t < 8) {
        const float4* p4 = (const float4*)(bufAll[0] + t * PSTRIDE);
        float s = 0.0f;
#pragma unroll
        for (int k = 0; k < 8; k++) {
            float4 v4 = p4[k];
            s += (v4.x + v4.y) + (v4.z + v4.w);
        }
        tninv_sh[t] = 1.0f / fmaxf(sqrtf(s), 1e-12f);
    }
    __syncthreads();

    // ---- main streaming loop: 5 s-values x 8 frames, one barrier per s ----
    for (int ss = 0; ss < SCHUNK; ss++) {
        const int p = ss & 1;
        float nrm[8];
#pragma unroll
        for (int i = 0; i < 8; i++) {
            const int f = ss * 8 + i;
            cp_wait<PF - 1>();                       // group f complete (exact)
            const int slot = f % RING;
            ulonglong2 A = ring[(slot * 2 + 0) * 256 + t];
            ulonglong2 B = ring[(slot * 2 + 1) * 256 + t];
            issue(f + PF);

            const unsigned long long ca0 = A.x, ca1 = A.y, cb0 = B.x, cb1 = B.y;
            unsigned long long acc[8];
#pragma unroll
            for (int k = 0; k < 8; k++) acc[k] = 0ull;
            unsigned long long n2 = 0ull;
            n2 = ffma2(ca0, ca0, n2);
            n2 = ffma2(ca1, ca1, n2);
            n2 = ffma2(cb0, cb0, n2);
            n2 = ffma2(cb1, cb1, n2);
#pragma unroll
            for (int k = 0; k < 8; k++) {
                acc[k] = ffma2(ca0, tva[k][0], acc[k]);
                acc[k] = ffma2(ca1, tva[k][1], acc[k]);
                acc[k] = ffma2(cb0, tva[k][2], acc[k]);
                acc[k] = ffma2(cb1, tva[k][3], acc[k]);
            }
            nrm[i] = pairsum(n2);
            float d[8];
#pragma unroll
            for (int k = 0; k < 8; k++) d[k] = pairsum(acc[k]);
            reduce8_free(d);                         // select-free: d[0] = dot(i, perm)
            bufAll[p][(i * 8 + perm) * PSTRIDE + col32] = d[0];
        }
        reduce8_3(nrm, lane);                        // support norms (selecty, 1x/s)
        bufAll[p][(64 + bitrev3((int)(lane & 7))) * PSTRIDE + col32] = nrm[0];

        __syncthreads();                             // single barrier per s-iter
        if (t < 72) {                                // fold 32 partials -> dotsum[ss]
            const float4* p4 = (const float4*)(bufAll[p] + t * PSTRIDE);
            float ssum = 0.0f;
#pragma unroll
            for (int k = 0; k < 8; k++) {
                float4 v4 = p4[k];
                ssum += (v4.x + v4.y) + (v4.z + v4.w);
            }
            dotsum[ss][t] = (t < 64) ? ssum : 1.0f / fmaxf(sqrtf(ssum), 1e-12f);
        }
        // no second barrier: bufAll[p] reused only at ss+2, after barrier(ss+1)
    }

    // ---- all 10 DPs (5 s x 2 views) at once, in parallel lanes of warp 0 ----
    __syncthreads();
    if (w == 0) {
        const int  s5    = (lane < 10) ? (int)(lane >> 1) : 0;
        const bool tr    = (lane & 1) != 0;
        float r = dp8r(dotsum[s5], dotsum[s5] + 64, tninv_sh, tr);
        float o = __shfl_xor_sync(0xffffffffu, r, 1);
        if (lane < 10 && !tr)
            out[(chunk * SCHUNK + s5) * BSZ + b] = 0.5f * (r + o);
    }
}

extern "C" void kernel_launch(void* const* d_in, const int* in_sizes, int n_in,
                              void* d_out, int out_size) {
    const ulonglong2* sup = (const ulonglong2*)d_in[0];
    const ulonglong2* tgt = (const ulonglong2*)d_in[1];
    float* out = (float*)d_out;
    (void)in_sizes; (void)n_in; (void)out_size;

    const int smem_bytes = RING * 512 * 16;        // 80KB dynamic ring
    static bool attr_done = false;                  // idempotent; host-side only
    if (!attr_done) {
        cudaFuncSetAttribute(otam_kernel,
                             cudaFuncAttributeMaxDynamicSharedMemorySize,
                             smem_bytes);
        attr_done = true;
    }

    dim3 grid(BSZ, NCHUNK);
    otam_kernel<<<grid, THREADS, smem_bytes>>>(sup, tgt, out);
}

// round 16
// speedup vs baseline: 2.4385x; 1.0435x over previous
#include <cuda_runtime.h>
#include <cstdint>

#define NFRAMES 8
#define SEQLEN  25
#define BSZ     256
#define DF      16384
#define LAMF    0.1f
#define INVLAM  10.0f
#define SCHUNK  5
#define NCHUNK  5
#define THREADS 256
#define RINGP   5                    // pair slots (10 frames, 80KB)
#define PFP     4                    // pair prefetch depth (4 pairs = 64KB in flight)
#define NPAIR_TOT (SCHUNK * NFRAMES / 2)   // 20 pairs per CTA
#define PSTRIDE 36                   // 32 partial cols + 4 pad

// ---------- sm_103a packed fp32 FMA ----------
__device__ __forceinline__ unsigned long long ffma2(unsigned long long a,
                                                    unsigned long long b,
                                                    unsigned long long c) {
    unsigned long long d;
    asm("fma.rn.f32x2 %0, %1, %2, %3;" : "=l"(d) : "l"(a), "l"(b), "l"(c));
    return d;
}
__device__ __forceinline__ float pairsum(unsigned long long v) {
    float lo, hi;
    asm("mov.b64 {%0,%1}, %2;" : "=f"(lo), "=f"(hi) : "l"(v));
    return lo + hi;
}

__device__ __forceinline__ int bitrev3(int l) {
    return ((l & 1) << 2) | (l & 2) | ((l & 4) >> 2);
}

// SELECT-FREE multi-value reduction. Value slot k at lane l holds quantity
// (k ^ bitrev3(l&7)); afterwards v[0] at lane l = 8-lane-group sum of
// quantity bitrev3(l&7). 7 SHFL + 7 FADD, zero selects.
__device__ __forceinline__ void reduce8_free(float v[8]) {
#pragma unroll
    for (int k = 0; k < 4; k++) v[k] += __shfl_xor_sync(0xffffffffu, v[k + 4], 1);
#pragma unroll
    for (int k = 0; k < 2; k++) v[k] += __shfl_xor_sync(0xffffffffu, v[k + 2], 2);
    v[0] += __shfl_xor_sync(0xffffffffu, v[1], 4);
}

// selecty variant for identically-indexed values (support norms, 1x/s-iter)
__device__ __forceinline__ void reduce8_3(float v[8], unsigned lane) {
#pragma unroll
    for (int k = 0; k < 4; k++) {
        float send = (lane & 1) ? v[k] : v[k + 4];
        float keep = (lane & 1) ? v[k + 4] : v[k];
        v[k] = keep + __shfl_xor_sync(0xffffffffu, send, 1);
    }
#pragma unroll
    for (int k = 0; k < 2; k++) {
        float send = (lane & 2) ? v[k] : v[k + 2];
        float keep = (lane & 2) ? v[k + 2] : v[k];
        v[k] = keep + __shfl_xor_sync(0xffffffffu, send, 2);
    }
    {
        float send = (lane & 4) ? v[0] : v[1];
        float keep = (lane & 4) ? v[1] : v[0];
        v[0] = keep + __shfl_xor_sync(0xffffffffu, send, 4);
    }
}

// ---------- cp.async helpers ----------
__device__ __forceinline__ void cp16(unsigned smem_addr, const void* gptr) {
    asm volatile("cp.async.cg.shared.global [%0], [%1], 16;\n"
                 :: "r"(smem_addr), "l"(gptr));
}
__device__ __forceinline__ void cp_commit() {
    asm volatile("cp.async.commit_group;\n");
}
template <int N>
__device__ __forceinline__ void cp_wait() {
    asm volatile("cp.async.wait_group %0;\n" :: "n"(N));
}

// fast stable pairwise lam*logsumexp (MUFU ex2/lg2)
__device__ __forceinline__ float lsep(float a, float b) {
    float m = fmaxf(a, b);
    float d = fabsf(a - b);
    return fmaf(LAMF, __logf(1.0f + __expf(-d * INVLAM)), m);
}

// runtime-transposed OTAM soft-DP on the 8x8 matrix
__device__ float dp8r(const float* __restrict__ d,
                      const float* __restrict__ sn,
                      const float* __restrict__ tn, bool tr) {
    float prev[8];
#pragma unroll
    for (int r = 0; r < 8; r++) {
        int rr = tr ? 0 : r, cc = tr ? r : 0;
        prev[r] = d[rr * 8 + cc] * sn[rr] * tn[cc];
    }
#pragma unroll
    for (int c = 1; c < 8; c++) {
        float nw[8];
        {
            int rr = tr ? c : 0, cc = tr ? 0 : c;
            nw[0] = prev[0] + d[rr * 8 + cc] * sn[rr] * tn[cc];
        }
#pragma unroll
        for (int r = 1; r < 8; r++) {
            int rr = tr ? c : r, cc = tr ? r : c;
            nw[r] = lsep(prev[r - 1], prev[r]) + d[rr * 8 + cc] * sn[rr] * tn[cc];
        }
#pragma unroll
        for (int r = 0; r < 8; r++) prev[r] = nw[r];
    }
    float m = prev[0];
#pragma unroll
    for (int r = 1; r < 8; r++) m = fmaxf(m, prev[r]);
    float s = 0.0f;
#pragma unroll
    for (int r = 0; r < 8; r++) s += __expf((prev[r] - m) * INVLAM);
    return fmaf(LAMF, __logf(s), m);
}

__global__ void __launch_bounds__(THREADS, 2)
otam_kernel(const ulonglong2* __restrict__ sup,   // [25,256,16384] f32 as ull2
            const ulonglong2* __restrict__ tgt,   // [256,16384]    f32 as ull2
            float* __restrict__ out)              // [25,256]
{
    extern __shared__ ulonglong2 ring[];          // [RINGP][4][256] x 16B = 80KB

    __shared__ __align__(16) float bufAll[2][72 * PSTRIDE];  // double-buffered partials
    __shared__ float dotsum[SCHUNK][72];          // [s][0..63 dots | 64..71 sninv]
    __shared__ float tninv_sh[8];

    const int t     = threadIdx.x;
    const int w     = t >> 5;
    const unsigned lane = t & 31;
    const int g     = (int)(lane >> 3);           // 8-lane group 0..3
    const int col32 = w * 4 + g;                  // partial slot 0..31
    const int perm  = bitrev3((int)(lane & 7));   // data-placement permutation
    const int b     = blockIdx.x;
    const int chunk = blockIdx.y;

    unsigned ring_base = (unsigned)__cvta_generic_to_shared(ring);
    const ulonglong2* gbase = sup + ((size_t)(chunk * SCHUNK) * BSZ + b) * (DF / 4);
    const size_t sstride = (size_t)BSZ * (DF / 4);

    // issue one PAIR of frames (16KB group); always commits -> wait math exact
    auto issue_pair = [&](int pp) {
        if (pp < NPAIR_TOT) {
            const int f0 = pp * 2;
            const int sl = f0 >> 3, i = f0 & 7;   // i in {0,2,4,6}
            const ulonglong2* src = gbase + (size_t)sl * sstride + (size_t)i * 512;
            const int slot = pp % RINGP;
            cp16(ring_base + (unsigned)((slot * 4 + 0) * 256 + t) * 16, src + t);
            cp16(ring_base + (unsigned)((slot * 4 + 1) * 256 + t) * 16, src + 256 + t);
            cp16(ring_base + (unsigned)((slot * 4 + 2) * 256 + t) * 16, src + 512 + t);
            cp16(ring_base + (unsigned)((slot * 4 + 3) * 256 + t) * 16, src + 768 + t);
        }
        cp_commit();
    };

#pragma unroll
    for (int pp = 0; pp < PFP; pp++) issue_pair(pp);

    // ---- target frames, slot-PERMUTED: tva[k] holds frame (k ^ perm) ----
    const ulonglong2* tb = tgt + (size_t)b * (DF / 4);
    unsigned long long tva[8][4];
#pragma unroll
    for (int k = 0; k < 8; k++) {
        const int j = k ^ perm;
        ulonglong2 a = tb[j * 512 + t];
        ulonglong2 c = tb[j * 512 + 256 + t];
        tva[k][0] = a.x; tva[k][1] = a.y; tva[k][2] = c.x; tva[k][3] = c.y;
    }
    // ---- target norms: select-free reduce; lands at logical frame perm ----
    {
        float tn[8];
#pragma unroll
        for (int k = 0; k < 8; k++) {
            unsigned long long n2 = 0ull;
#pragma unroll
            for (int c = 0; c < 4; c++) n2 = ffma2(tva[k][c], tva[k][c], n2);
            tn[k] = pairsum(n2);
        }
        reduce8_free(tn);
        bufAll[0][perm * PSTRIDE + col32] = tn[0];
    }
    __syncthreads();
    if (t < 8) {
        const float4* p4 = (const float4*)(bufAll[0] + t * PSTRIDE);
        float s = 0.0f;
#pragma unroll
        for (int k = 0; k < 8; k++) {
            float4 v4 = p4[k];
            s += (v4.x + v4.y) + (v4.z + v4.w);
        }
        tninv_sh[t] = 1.0f / fmaxf(sqrtf(s), 1e-12f);
    }
    __syncthreads();

    // ---- main loop: 5 s-values x 4 pairs; ONE wait per two frames ----
    for (int ss = 0; ss < SCHUNK; ss++) {
        const int p = ss & 1;
        float nrm[8];
#pragma unroll
        for (int ii = 0; ii < 4; ii++) {
            const int pp = ss * 4 + ii;
            cp_wait<PFP - 1>();                      // pair pp resident (exact)
            const int slot = pp % RINGP;
            ulonglong2 A0 = ring[(slot * 4 + 0) * 256 + t];
            ulonglong2 A1 = ring[(slot * 4 + 1) * 256 + t];
            ulonglong2 B0 = ring[(slot * 4 + 2) * 256 + t];
            ulonglong2 B1 = ring[(slot * 4 + 3) * 256 + t];
            issue_pair(pp + PFP);

            // ---- frame 2*ii ----
            {
                const unsigned long long ca0 = A0.x, ca1 = A0.y, cb0 = A1.x, cb1 = A1.y;
                unsigned long long acc[8];
#pragma unroll
                for (int k = 0; k < 8; k++) acc[k] = 0ull;
                unsigned long long n2 = 0ull;
                n2 = ffma2(ca0, ca0, n2);
                n2 = ffma2(ca1, ca1, n2);
                n2 = ffma2(cb0, cb0, n2);
                n2 = ffma2(cb1, cb1, n2);
#pragma unroll
                for (int k = 0; k < 8; k++) {
                    acc[k] = ffma2(ca0, tva[k][0], acc[k]);
                    acc[k] = ffma2(ca1, tva[k][1], acc[k]);
                    acc[k] = ffma2(cb0, tva[k][2], acc[k]);
                    acc[k] = ffma2(cb1, tva[k][3], acc[k]);
                }
                nrm[ii * 2] = pairsum(n2);
                float d[8];
#pragma unroll
                for (int k = 0; k < 8; k++) d[k] = pairsum(acc[k]);
                reduce8_free(d);
                bufAll[p][((ii * 2) * 8 + perm) * PSTRIDE + col32] = d[0];
            }
            // ---- frame 2*ii+1 (no wait: data already resident) ----
            {
                const unsigned long long ca0 = B0.x, ca1 = B0.y, cb0 = B1.x, cb1 = B1.y;
                unsigned long long acc[8];
#pragma unroll
                for (int k = 0; k < 8; k++) acc[k] = 0ull;
                unsigned long long n2 = 0ull;
                n2 = ffma2(ca0, ca0, n2);
                n2 = ffma2(ca1, ca1, n2);
                n2 = ffma2(cb0, cb0, n2);
                n2 = ffma2(cb1, cb1, n2);
#pragma unroll
                for (int k = 0; k < 8; k++) {
                    acc[k] = ffma2(ca0, tva[k][0], acc[k]);
                    acc[k] = ffma2(ca1, tva[k][1], acc[k]);
                    acc[k] = ffma2(cb0, tva[k][2], acc[k]);
                    acc[k] = ffma2(cb1, tva[k][3], acc[k]);
                }
                nrm[ii * 2 + 1] = pairsum(n2);
                float d[8];
#pragma unroll
                for (int k = 0; k < 8; k++) d[k] = pairsum(acc[k]);
                reduce8_free(d);
                bufAll[p][((ii * 2 + 1) * 8 + perm) * PSTRIDE + col32] = d[0];
            }
        }
        reduce8_3(nrm, lane);                        // support norms (1x per s)
        bufAll[p][(64 + bitrev3((int)(lane & 7))) * PSTRIDE + col32] = nrm[0];

        __syncthreads();                             // single barrier per s-iter
        if (t < 72) {                                // fold 32 partials -> dotsum[ss]
            const float4* p4 = (const float4*)(bufAll[p] + t * PSTRIDE);
            float ssum = 0.0f;
#pragma unroll
            for (int k = 0; k < 8; k++) {
                float4 v4 = p4[k];
                ssum += (v4.x + v4.y) + (v4.z + v4.w);
            }
            dotsum[ss][t] = (t < 64) ? ssum : 1.0f / fmaxf(sqrtf(ssum), 1e-12f);
        }
        // no second barrier: bufAll[p] reused only at ss+2, after barrier(ss+1)
    }

    // ---- all 10 DPs (5 s x 2 views) in parallel lanes of warp 0 ----
    __syncthreads();
    if (w == 0) {
        const int  s5 = (lane < 10) ? (int)(lane >> 1) : 0;
        const bool tr = (lane & 1) != 0;
        float r = dp8r(dotsum[s5], dotsum[s5] + 64, tninv_sh, tr);
        float o = __shfl_xor_sync(0xffffffffu, r, 1);
        if (lane < 10 && !tr)
            out[(chunk * SCHUNK + s5) * BSZ + b] = 0.5f * (r + o);
    }
}

extern "C" void kernel_launch(void* const* d_in, const int* in_sizes, int n_in,
                              void* d_out, int out_size) {
    const ulonglong2* sup = (const ulonglong2*)d_in[0];
    const ulonglong2* tgt = (const ulonglong2*)d_in[1];
    float* out = (float*)d_out;
    (void)in_sizes; (void)n_in; (void)out_size;

    const int smem_bytes = RINGP * 4 * 256 * 16;   // 80KB dynamic ring
    static bool attr_done = false;                  // idempotent; host-side only
    if (!attr_done) {
        cudaFuncSetAttribute(otam_kernel,
                             cudaFuncAttributeMaxDynamicSharedMemorySize,
                             smem_bytes);
        attr_done = true;
    }

    dim3 grid(BSZ, NCHUNK);
    otam_kernel<<<grid, THREADS, smem_bytes>>>(sup, tgt, out);
}